// round 14
// baseline (speedup 1.0000x reference)
#include <cuda_runtime.h>
#include <cuda_bf16.h>
#include <stdint.h>

#define N_NODES 50000
#define D 256
#define N_EDGES 400000
#define KP (D / 2)          // 128 packed k-pair words per row

// Scratch — device globals (no allocations allowed).
__device__ float    g_h[(size_t)N_NODES * D];    // GEMM output (per layer)
__device__ uint32_t g_ah[(size_t)N_NODES * KP];  // packed bf16x2 hi of A (x / layer-1 act)
__device__ uint32_t g_al[(size_t)N_NODES * KP];  // packed bf16x2 lo of A
__device__ uint32_t g_w1h[(size_t)KP * D], g_w1l[(size_t)KP * D];  // W1 split [k2][n]
__device__ uint32_t g_w2h[(size_t)KP * D], g_w2l[(size_t)KP * D];  // W2 split [k2][n]
__device__ float    g_dinv[N_NODES];
__device__ int      g_cnt[N_NODES];
__device__ int      g_cursor[N_NODES];
__device__ int      g_rowstart[N_NODES + 1];
__device__ int      g_csr_src[N_EDGES];
__device__ float    g_csr_w[N_EDGES];
__device__ int      g_src[N_EDGES];
__device__ int      g_dst[N_EDGES];
__device__ int      g_is64;

// ---------------------------------------------------------------------------
// prep 1: zero cnt/cursor + detect edge-index dtype (fused)
// ---------------------------------------------------------------------------
__global__ void prep_zero_detect_kernel(const unsigned int* __restrict__ ei32,
                                        int* cnt, int* cursor) {
    int i = blockIdx.x * blockDim.x + threadIdx.x;
    if (i < N_NODES) { cnt[i] = 0; cursor[i] = 0; }
    if (i == 0) {
        int is64 = 1;
        for (int k = 0; k < 64; k++)
            if (ei32[2 * k + 1] != 0u) { is64 = 0; break; }
        g_is64 = is64;
    }
}

// ---------------------------------------------------------------------------
// prep 2: index conversion + degree count (fused)
// ---------------------------------------------------------------------------
__global__ void convert_count_kernel(const void* __restrict__ ei,
                                     int* __restrict__ srcOut, int* __restrict__ dstOut,
                                     int* cnt) {
    int i = blockIdx.x * blockDim.x + threadIdx.x;
    if (i >= N_EDGES) return;
    int s, t;
    if (g_is64) {
        const long long* e = (const long long*)ei;
        s = (int)e[i];
        t = (int)e[i + N_EDGES];
    } else {
        const int* e = (const int*)ei;
        s = e[i];
        t = e[i + N_EDGES];
    }
    srcOut[i] = s;
    dstOut[i] = t;
    atomicAdd(&cnt[t], 1);
}

// ---------------------------------------------------------------------------
// prep 3: single-block exclusive scan over counts + dinv (fused)
// ---------------------------------------------------------------------------
__global__ __launch_bounds__(1024) void scan_dinv_kernel(const int* __restrict__ cnt,
                                                         int* __restrict__ rowstart,
                                                         float* __restrict__ dinv) {
    __shared__ int sums[1024];
    const int tid = threadIdx.x;
    const int CH = (N_NODES + 1023) / 1024;
    const int base = tid * CH;
    int s = 0;
    for (int i = 0; i < CH; i++) {
        int idx = base + i;
        if (idx < N_NODES) s += cnt[idx];
    }
    sums[tid] = s;
    __syncthreads();
    for (int off = 1; off < 1024; off <<= 1) {
        int u = (tid >= off) ? sums[tid - off] : 0;
        __syncthreads();
        sums[tid] += u;
        __syncthreads();
    }
    int run = (tid == 0) ? 0 : sums[tid - 1];
    for (int i = 0; i < CH; i++) {
        int idx = base + i;
        if (idx < N_NODES) {
            rowstart[idx] = run;
            int c = cnt[idx];
            run += c;
            dinv[idx] = rsqrtf((float)(c + 1));  // +1 self-loop
        }
    }
    if (tid == 1023) rowstart[N_NODES] = sums[1023];
}

// ---------------------------------------------------------------------------
// prep 4: CSR bucket fill
// ---------------------------------------------------------------------------
__global__ void fill_kernel(const int* __restrict__ src, const int* __restrict__ dst,
                            const int* __restrict__ rowstart, int* cursor,
                            const float* __restrict__ dinv,
                            int* __restrict__ csr_src, float* __restrict__ csr_w) {
    int i = blockIdx.x * blockDim.x + threadIdx.x;
    if (i >= N_EDGES) return;
    int s = src[i], t = dst[i];
    int pos = rowstart[t] + atomicAdd(&cursor[t], 1);
    csr_src[pos] = s;
    csr_w[pos] = dinv[s] * dinv[t];
}

// ---------------------------------------------------------------------------
// prep 5: both weight splits in one launch.
// fp32 [256(k)][256(n)] -> u32 [128(k2)][256(n)] packed bf16x2 hi/lo
// ---------------------------------------------------------------------------
__global__ void split_both_w_kernel(const float* __restrict__ W1f,
                                    const float* __restrict__ W2f,
                                    uint32_t* __restrict__ w1h, uint32_t* __restrict__ w1l,
                                    uint32_t* __restrict__ w2h, uint32_t* __restrict__ w2l) {
    int i = blockIdx.x * blockDim.x + threadIdx.x;
    if (i >= 2 * KP * D) return;
    const bool first = (i < KP * D);
    const float* W = first ? W1f : W2f;
    uint32_t* hi = first ? w1h : w2h;
    uint32_t* lo = first ? w1l : w2l;
    int j = first ? i : i - KP * D;
    int k2 = j >> 8;
    int n = j & 255;
    float x0 = W[(size_t)(2 * k2) * D + n];
    float x1 = W[(size_t)(2 * k2 + 1) * D + n];
    __nv_bfloat162 h2 = __floats2bfloat162_rn(x0, x1);
    float r0 = x0 - __bfloat162float(h2.x);
    float r1 = x1 - __bfloat162float(h2.y);
    __nv_bfloat162 l2 = __floats2bfloat162_rn(r0, r1);
    hi[j] = *(uint32_t*)&h2;
    lo[j] = *(uint32_t*)&l2;
}

// ---------------------------------------------------------------------------
// prep 6: split input x (row-major k-pairs)
// ---------------------------------------------------------------------------
__global__ void split_rowmajor_kernel(const float* __restrict__ in,
                                      uint32_t* __restrict__ hi, uint32_t* __restrict__ lo,
                                      int nPairs) {
    int i = blockIdx.x * blockDim.x + threadIdx.x;
    if (i >= nPairs) return;
    float2 v = ((const float2*)in)[i];
    __nv_bfloat162 h2 = __floats2bfloat162_rn(v.x, v.y);
    float r0 = v.x - __bfloat162float(h2.x);
    float r1 = v.y - __bfloat162float(h2.y);
    __nv_bfloat162 l2 = __floats2bfloat162_rn(r0, r1);
    hi[i] = *(uint32_t*)&h2;
    lo[i] = *(uint32_t*)&l2;
}

// ---------------------------------------------------------------------------
// bf16 split tensor-core GEMM: C = Ah@Bh + Ah@Bl + Al@Bh  (fp32 accum)
// Block 128x128, 8 warps (warp tile 32x64), mma.sync m16n8k16.bf16.
// Double-buffered SMEM, 24 iterations = 3 phases x 8 k-tiles. (verified R13)
// ---------------------------------------------------------------------------
#define BM 128
#define BN 128
#define KW 16   // k2 words per tile (=32 k values)
#define ASTRIDE (KW + 4)   // 20 words: conflict-free
#define BSTRIDE (BN + 8)   // 136 words: conflict-free

__device__ __forceinline__ void mma_bf16(float* c, const uint32_t* a, const uint32_t* b) {
    asm volatile(
        "mma.sync.aligned.m16n8k16.row.col.f32.bf16.bf16.f32 "
        "{%0,%1,%2,%3}, {%4,%5,%6,%7}, {%8,%9}, {%0,%1,%2,%3};"
        : "+f"(c[0]), "+f"(c[1]), "+f"(c[2]), "+f"(c[3])
        : "r"(a[0]), "r"(a[1]), "r"(a[2]), "r"(a[3]), "r"(b[0]), "r"(b[1]));
}

__global__ __launch_bounds__(256) void bgemm_kernel(
    const uint32_t* __restrict__ Ah, const uint32_t* __restrict__ Al,
    const uint32_t* __restrict__ Bh, const uint32_t* __restrict__ Bl,
    float* __restrict__ C, int M) {
    __shared__ uint32_t As2[2][BM * ASTRIDE];
    __shared__ uint32_t Bs2[2][KW * BSTRIDE];

    const int tid = threadIdx.x;
    const int lane = tid & 31;
    const int wid = tid >> 5;
    const int warpM = wid & 3;
    const int warpN = wid >> 2;
    const int g = lane >> 2;
    const int t = lane & 3;
    const int rowBase = blockIdx.x * BM;
    const int colBase = blockIdx.y * BN;

    const int q0 = tid * 2, q1 = q0 + 1;
    const int ar0 = q0 >> 2, aw0 = (q0 & 3) << 2;
    const int ar1 = q1 >> 2, aw1 = (q1 & 3) << 2;
    const int grow0 = rowBase + ar0, grow1 = rowBase + ar1;
    const int bq0 = tid * 2, bq1 = bq0 + 1;
    const int br0 = bq0 >> 5, bw0 = (bq0 & 31) << 2;
    const int br1 = bq1 >> 5, bw1 = (bq1 & 31) << 2;

    const uint32_t* APtrs[3] = {Ah, Ah, Al};
    const uint32_t* BPtrs[3] = {Bh, Bl, Bh};

    float c[2][8][4];
#pragma unroll
    for (int mt = 0; mt < 2; mt++)
#pragma unroll
        for (int nt = 0; nt < 8; nt++)
#pragma unroll
            for (int r = 0; r < 4; r++) c[mt][nt][r] = 0.0f;

    uint4 pa0, pa1, pb0, pb1;
    {
        const uint32_t* Ap = APtrs[0];
        const uint32_t* Bp = BPtrs[0];
        pa0 = (grow0 < M) ? *(const uint4*)(Ap + (size_t)grow0 * KP + aw0)
                          : make_uint4(0, 0, 0, 0);
        pa1 = (grow1 < M) ? *(const uint4*)(Ap + (size_t)grow1 * KP + aw1)
                          : make_uint4(0, 0, 0, 0);
        pb0 = *(const uint4*)(Bp + (size_t)br0 * D + colBase + bw0);
        pb1 = *(const uint4*)(Bp + (size_t)br1 * D + colBase + bw1);
        *(uint4*)&As2[0][ar0 * ASTRIDE + aw0] = pa0;
        *(uint4*)&As2[0][ar1 * ASTRIDE + aw1] = pa1;
        *(uint4*)&Bs2[0][br0 * BSTRIDE + bw0] = pb0;
        *(uint4*)&Bs2[0][br1 * BSTRIDE + bw1] = pb1;
    }
    __syncthreads();

    for (int it = 0; it < 24; it++) {
        const int cur = it & 1;
        const bool more = (it + 1 < 24);
        if (more) {
            int nx = it + 1;
            int p = nx >> 3;
            int kw0 = (nx & 7) * KW;
            const uint32_t* Ap = APtrs[p];
            const uint32_t* Bp = BPtrs[p];
            pa0 = (grow0 < M) ? *(const uint4*)(Ap + (size_t)grow0 * KP + kw0 + aw0)
                              : make_uint4(0, 0, 0, 0);
            pa1 = (grow1 < M) ? *(const uint4*)(Ap + (size_t)grow1 * KP + kw0 + aw1)
                              : make_uint4(0, 0, 0, 0);
            pb0 = *(const uint4*)(Bp + (size_t)(kw0 + br0) * D + colBase + bw0);
            pb1 = *(const uint4*)(Bp + (size_t)(kw0 + br1) * D + colBase + bw1);
        }

        const uint32_t* Asc = As2[cur];
        const uint32_t* Bsc = Bs2[cur];
#pragma unroll
        for (int ks = 0; ks < 2; ks++) {
            const int kb = ks * 8;
            uint32_t a[2][4], b[8][2];
#pragma unroll
            for (int mt = 0; mt < 2; mt++) {
                int m0 = warpM * 32 + mt * 16;
                a[mt][0] = Asc[(m0 + g) * ASTRIDE + kb + t];
                a[mt][1] = Asc[(m0 + g + 8) * ASTRIDE + kb + t];
                a[mt][2] = Asc[(m0 + g) * ASTRIDE + kb + t + 4];
                a[mt][3] = Asc[(m0 + g + 8) * ASTRIDE + kb + t + 4];
            }
#pragma unroll
            for (int nt = 0; nt < 8; nt++) {
                int n0 = warpN * 64 + nt * 8;
                b[nt][0] = Bsc[(kb + t) * BSTRIDE + n0 + g];
                b[nt][1] = Bsc[(kb + t + 4) * BSTRIDE + n0 + g];
            }
#pragma unroll
            for (int mt = 0; mt < 2; mt++)
#pragma unroll
                for (int nt = 0; nt < 8; nt++)
                    mma_bf16(c[mt][nt], a[mt], b[nt]);
        }

        if (more) {
            const int nxt = 1 - cur;
            *(uint4*)&As2[nxt][ar0 * ASTRIDE + aw0] = pa0;
            *(uint4*)&As2[nxt][ar1 * ASTRIDE + aw1] = pa1;
            *(uint4*)&Bs2[nxt][br0 * BSTRIDE + bw0] = pb0;
            *(uint4*)&Bs2[nxt][br1 * BSTRIDE + bw1] = pb1;
        }
        __syncthreads();
    }

#pragma unroll
    for (int mt = 0; mt < 2; mt++) {
#pragma unroll
        for (int nt = 0; nt < 8; nt++) {
            int row0 = rowBase + warpM * 32 + mt * 16 + g;
            int col = colBase + warpN * 64 + nt * 8 + t * 2;
            if (row0 < M)
                *(float2*)(C + (size_t)row0 * D + col) =
                    make_float2(c[mt][nt][0], c[mt][nt][1]);
            if (row0 + 8 < M)
                *(float2*)(C + (size_t)(row0 + 8) * D + col) =
                    make_float2(c[mt][nt][2], c[mt][nt][3]);
        }
    }
}

// ---------------------------------------------------------------------------
// Fused gather: warp-per-node, edge loop unrolled x2 with index prefetch.
// acc = h[n,:]*dinv^2 + sum_in-edges h[src,:]*w + b; relu.
// writePacked=1: emit bf16 hi/lo packed (feeds next GEMM). Else write fp32.
// ---------------------------------------------------------------------------
__global__ __launch_bounds__(256) void gather_kernel(
    const float* __restrict__ h,
    const int* __restrict__ rowstart,
    const int* __restrict__ csr_src,
    const float* __restrict__ csr_w,
    const float* __restrict__ dinv,
    const float* __restrict__ bias,
    float* __restrict__ out,
    uint32_t* __restrict__ outHi,
    uint32_t* __restrict__ outLo,
    int writePacked) {
    int node = (blockIdx.x * blockDim.x + threadIdx.x) >> 5;
    if (node >= N_NODES) return;
    int lane = threadIdx.x & 31;

    float dv = dinv[node];
    float w0 = dv * dv;
    const float4* selfp = (const float4*)(h + (size_t)node * D);
    float4 a0 = selfp[lane];
    float4 a1 = selfp[lane + 32];
    a0.x *= w0; a0.y *= w0; a0.z *= w0; a0.w *= w0;
    a1.x *= w0; a1.y *= w0; a1.z *= w0; a1.w *= w0;

    int beg = rowstart[node];
    int end = rowstart[node + 1];
    int j = beg;
    for (; j + 1 < end; j += 2) {
        int sA = __ldg(&csr_src[j]);
        int sB = __ldg(&csr_src[j + 1]);
        float wA = __ldg(&csr_w[j]);
        float wB = __ldg(&csr_w[j + 1]);
        const float4* spA = (const float4*)(h + (size_t)sA * D);
        const float4* spB = (const float4*)(h + (size_t)sB * D);
        float4 vA0 = spA[lane];
        float4 vA1 = spA[lane + 32];
        float4 vB0 = spB[lane];
        float4 vB1 = spB[lane + 32];
        a0.x = fmaf(vA0.x, wA, a0.x); a0.y = fmaf(vA0.y, wA, a0.y);
        a0.z = fmaf(vA0.z, wA, a0.z); a0.w = fmaf(vA0.w, wA, a0.w);
        a1.x = fmaf(vA1.x, wA, a1.x); a1.y = fmaf(vA1.y, wA, a1.y);
        a1.z = fmaf(vA1.z, wA, a1.z); a1.w = fmaf(vA1.w, wA, a1.w);
        a0.x = fmaf(vB0.x, wB, a0.x); a0.y = fmaf(vB0.y, wB, a0.y);
        a0.z = fmaf(vB0.z, wB, a0.z); a0.w = fmaf(vB0.w, wB, a0.w);
        a1.x = fmaf(vB1.x, wB, a1.x); a1.y = fmaf(vB1.y, wB, a1.y);
        a1.z = fmaf(vB1.z, wB, a1.z); a1.w = fmaf(vB1.w, wB, a1.w);
    }
    if (j < end) {
        int s = __ldg(&csr_src[j]);
        float w = __ldg(&csr_w[j]);
        const float4* sp = (const float4*)(h + (size_t)s * D);
        float4 v0 = sp[lane];
        float4 v1 = sp[lane + 32];
        a0.x = fmaf(v0.x, w, a0.x); a0.y = fmaf(v0.y, w, a0.y);
        a0.z = fmaf(v0.z, w, a0.z); a0.w = fmaf(v0.w, w, a0.w);
        a1.x = fmaf(v1.x, w, a1.x); a1.y = fmaf(v1.y, w, a1.y);
        a1.z = fmaf(v1.z, w, a1.z); a1.w = fmaf(v1.w, w, a1.w);
    }

    const float4* b4 = (const float4*)bias;
    float4 bb0 = b4[lane];
    float4 bb1 = b4[lane + 32];
    a0.x = fmaxf(a0.x + bb0.x, 0.f); a0.y = fmaxf(a0.y + bb0.y, 0.f);
    a0.z = fmaxf(a0.z + bb0.z, 0.f); a0.w = fmaxf(a0.w + bb0.w, 0.f);
    a1.x = fmaxf(a1.x + bb1.x, 0.f); a1.y = fmaxf(a1.y + bb1.y, 0.f);
    a1.z = fmaxf(a1.z + bb1.z, 0.f); a1.w = fmaxf(a1.w + bb1.w, 0.f);

    if (writePacked) {
        size_t base = (size_t)node * KP;
        __nv_bfloat162 h00 = __floats2bfloat162_rn(a0.x, a0.y);
        __nv_bfloat162 h01 = __floats2bfloat162_rn(a0.z, a0.w);
        __nv_bfloat162 h10 = __floats2bfloat162_rn(a1.x, a1.y);
        __nv_bfloat162 h11 = __floats2bfloat162_rn(a1.z, a1.w);
        __nv_bfloat162 l00 = __floats2bfloat162_rn(a0.x - __bfloat162float(h00.x),
                                                   a0.y - __bfloat162float(h00.y));
        __nv_bfloat162 l01 = __floats2bfloat162_rn(a0.z - __bfloat162float(h01.x),
                                                   a0.w - __bfloat162float(h01.y));
        __nv_bfloat162 l10 = __floats2bfloat162_rn(a1.x - __bfloat162float(h10.x),
                                                   a1.y - __bfloat162float(h10.y));
        __nv_bfloat162 l11 = __floats2bfloat162_rn(a1.z - __bfloat162float(h11.x),
                                                   a1.w - __bfloat162float(h11.y));
        *(uint2*)&outHi[base + 2 * lane] = make_uint2(*(uint32_t*)&h00, *(uint32_t*)&h01);
        *(uint2*)&outHi[base + 64 + 2 * lane] = make_uint2(*(uint32_t*)&h10, *(uint32_t*)&h11);
        *(uint2*)&outLo[base + 2 * lane] = make_uint2(*(uint32_t*)&l00, *(uint32_t*)&l01);
        *(uint2*)&outLo[base + 64 + 2 * lane] = make_uint2(*(uint32_t*)&l10, *(uint32_t*)&l11);
    } else {
        float4* op = (float4*)(out + (size_t)node * D);
        op[lane] = a0;
        op[lane + 32] = a1;
    }
}

// ---------------------------------------------------------------------------
// Launch
// ---------------------------------------------------------------------------
extern "C" void kernel_launch(void* const* d_in, const int* in_sizes, int n_in,
                              void* d_out, int out_size) {
    const float* x = (const float*)d_in[0];
    const void* ei = d_in[1];
    const float* W1 = (const float*)d_in[2];
    const float* b1 = (const float*)d_in[3];
    const float* W2 = (const float*)d_in[4];
    const float* b2 = (const float*)d_in[5];
    float* out = (float*)d_out;

    float *h, *dinv, *csr_w;
    int *srcI, *dstI, *cnt, *cursor, *rowstart, *csr_src;
    uint32_t *ah, *al, *w1h, *w1l, *w2h, *w2l;
    cudaGetSymbolAddress((void**)&h, g_h);
    cudaGetSymbolAddress((void**)&dinv, g_dinv);
    cudaGetSymbolAddress((void**)&cnt, g_cnt);
    cudaGetSymbolAddress((void**)&cursor, g_cursor);
    cudaGetSymbolAddress((void**)&rowstart, g_rowstart);
    cudaGetSymbolAddress((void**)&csr_src, g_csr_src);
    cudaGetSymbolAddress((void**)&csr_w, g_csr_w);
    cudaGetSymbolAddress((void**)&srcI, g_src);
    cudaGetSymbolAddress((void**)&dstI, g_dst);
    cudaGetSymbolAddress((void**)&ah, g_ah);
    cudaGetSymbolAddress((void**)&al, g_al);
    cudaGetSymbolAddress((void**)&w1h, g_w1h);
    cudaGetSymbolAddress((void**)&w1l, g_w1l);
    cudaGetSymbolAddress((void**)&w2h, g_w2h);
    cudaGetSymbolAddress((void**)&w2l, g_w2l);

    const int TPB = 256;
    const int gN = (N_NODES + TPB - 1) / TPB;
    const int gE = (N_EDGES + TPB - 1) / TPB;
    const int gGather = (int)(((long long)N_NODES * 32 + TPB - 1) / TPB);
    const int nPairsA = N_NODES * KP;
    const int gSplitA = (nPairsA + TPB - 1) / TPB;
    const int gSplitW2 = (2 * KP * D + TPB - 1) / TPB;
    dim3 gGemm((N_NODES + BM - 1) / BM, D / BN);   // (391, 1) with BN=128 -> (391, 2)

    // ---- prep (6 launches) ----
    prep_zero_detect_kernel<<<gN, TPB>>>((const unsigned int*)ei, cnt, cursor);
    convert_count_kernel<<<gE, TPB>>>(ei, srcI, dstI, cnt);
    scan_dinv_kernel<<<1, 1024>>>(cnt, rowstart, dinv);
    fill_kernel<<<gE, TPB>>>(srcI, dstI, rowstart, cursor, dinv, csr_src, csr_w);
    split_both_w_kernel<<<gSplitW2, TPB>>>(W1, W2, w1h, w1l, w2h, w2l);
    split_rowmajor_kernel<<<gSplitA, TPB>>>(x, ah, al, nPairsA);

    // ---- layer 1 ----
    bgemm_kernel<<<gGemm, TPB>>>(ah, al, w1h, w1l, h, N_NODES);
    gather_kernel<<<gGather, TPB>>>(h, rowstart, csr_src, csr_w, dinv, b1,
                                    (float*)nullptr, ah, al, 1);

    // ---- layer 2 ----
    bgemm_kernel<<<gGemm, TPB>>>(ah, al, w2h, w2l, h, N_NODES);
    gather_kernel<<<gGather, TPB>>>(h, rowstart, csr_src, csr_w, dinv, b2,
                                    out, (uint32_t*)nullptr, (uint32_t*)nullptr, 0);
}

// round 16
// speedup vs baseline: 1.0271x; 1.0271x over previous
#include <cuda_runtime.h>
#include <cuda_bf16.h>
#include <stdint.h>

#define N_NODES 50000
#define D 256
#define N_EDGES 400000
#define KP (D / 2)          // 128 packed k-pair words per row

// Scratch — device globals (no allocations allowed).
__device__ float    g_h[(size_t)N_NODES * D];    // GEMM output (per layer)
__device__ uint32_t g_ah[(size_t)N_NODES * KP];  // packed bf16x2 hi of A (x / layer-1 act)
__device__ uint32_t g_al[(size_t)N_NODES * KP];  // packed bf16x2 lo of A
__device__ uint32_t g_w1h[(size_t)KP * D], g_w1l[(size_t)KP * D];  // W1 split [k2][n]
__device__ uint32_t g_w2h[(size_t)KP * D], g_w2l[(size_t)KP * D];  // W2 split [k2][n]
__device__ float    g_dinv[N_NODES];
__device__ int      g_cnt[N_NODES];
__device__ int      g_cursor[N_NODES];
__device__ int      g_rowstart[N_NODES + 1];
__device__ int      g_csr_src[N_EDGES];
__device__ float    g_csr_w[N_EDGES];
__device__ int      g_src[N_EDGES];
__device__ int      g_dst[N_EDGES];
__device__ int      g_is64;

// ---------------------------------------------------------------------------
// prep 1: zero cnt/cursor + detect edge-index dtype (fused)
// ---------------------------------------------------------------------------
__global__ void prep_zero_detect_kernel(const unsigned int* __restrict__ ei32,
                                        int* cnt, int* cursor) {
    int i = blockIdx.x * blockDim.x + threadIdx.x;
    if (i < N_NODES) { cnt[i] = 0; cursor[i] = 0; }
    if (i == 0) {
        int is64 = 1;
        for (int k = 0; k < 64; k++)
            if (ei32[2 * k + 1] != 0u) { is64 = 0; break; }
        g_is64 = is64;
    }
}

// ---------------------------------------------------------------------------
// prep 2: index conversion + degree count (fused)
// ---------------------------------------------------------------------------
__global__ void convert_count_kernel(const void* __restrict__ ei,
                                     int* __restrict__ srcOut, int* __restrict__ dstOut,
                                     int* cnt) {
    int i = blockIdx.x * blockDim.x + threadIdx.x;
    if (i >= N_EDGES) return;
    int s, t;
    if (g_is64) {
        const long long* e = (const long long*)ei;
        s = (int)e[i];
        t = (int)e[i + N_EDGES];
    } else {
        const int* e = (const int*)ei;
        s = e[i];
        t = e[i + N_EDGES];
    }
    srcOut[i] = s;
    dstOut[i] = t;
    atomicAdd(&cnt[t], 1);
}

// ---------------------------------------------------------------------------
// prep 3: single-block exclusive scan over counts + dinv (fused)
// ---------------------------------------------------------------------------
__global__ __launch_bounds__(1024) void scan_dinv_kernel(const int* __restrict__ cnt,
                                                         int* __restrict__ rowstart,
                                                         float* __restrict__ dinv) {
    __shared__ int sums[1024];
    const int tid = threadIdx.x;
    const int CH = (N_NODES + 1023) / 1024;
    const int base = tid * CH;
    int s = 0;
    for (int i = 0; i < CH; i++) {
        int idx = base + i;
        if (idx < N_NODES) s += cnt[idx];
    }
    sums[tid] = s;
    __syncthreads();
    for (int off = 1; off < 1024; off <<= 1) {
        int u = (tid >= off) ? sums[tid - off] : 0;
        __syncthreads();
        sums[tid] += u;
        __syncthreads();
    }
    int run = (tid == 0) ? 0 : sums[tid - 1];
    for (int i = 0; i < CH; i++) {
        int idx = base + i;
        if (idx < N_NODES) {
            rowstart[idx] = run;
            int c = cnt[idx];
            run += c;
            dinv[idx] = rsqrtf((float)(c + 1));  // +1 self-loop
        }
    }
    if (tid == 1023) rowstart[N_NODES] = sums[1023];
}

// ---------------------------------------------------------------------------
// prep 4: CSR bucket fill
// ---------------------------------------------------------------------------
__global__ void fill_kernel(const int* __restrict__ src, const int* __restrict__ dst,
                            const int* __restrict__ rowstart, int* cursor,
                            const float* __restrict__ dinv,
                            int* __restrict__ csr_src, float* __restrict__ csr_w) {
    int i = blockIdx.x * blockDim.x + threadIdx.x;
    if (i >= N_EDGES) return;
    int s = src[i], t = dst[i];
    int pos = rowstart[t] + atomicAdd(&cursor[t], 1);
    csr_src[pos] = s;
    csr_w[pos] = dinv[s] * dinv[t];
}

// ---------------------------------------------------------------------------
// prep 5: both weight splits in one launch.
// fp32 [256(k)][256(n)] -> u32 [128(k2)][256(n)] packed bf16x2 hi/lo
// ---------------------------------------------------------------------------
__global__ void split_both_w_kernel(const float* __restrict__ W1f,
                                    const float* __restrict__ W2f,
                                    uint32_t* __restrict__ w1h, uint32_t* __restrict__ w1l,
                                    uint32_t* __restrict__ w2h, uint32_t* __restrict__ w2l) {
    int i = blockIdx.x * blockDim.x + threadIdx.x;
    if (i >= 2 * KP * D) return;
    const bool first = (i < KP * D);
    const float* W = first ? W1f : W2f;
    uint32_t* hi = first ? w1h : w2h;
    uint32_t* lo = first ? w1l : w2l;
    int j = first ? i : i - KP * D;
    int k2 = j >> 8;
    int n = j & 255;
    float x0 = W[(size_t)(2 * k2) * D + n];
    float x1 = W[(size_t)(2 * k2 + 1) * D + n];
    __nv_bfloat162 h2 = __floats2bfloat162_rn(x0, x1);
    float r0 = x0 - __bfloat162float(h2.x);
    float r1 = x1 - __bfloat162float(h2.y);
    __nv_bfloat162 l2 = __floats2bfloat162_rn(r0, r1);
    hi[j] = *(uint32_t*)&h2;
    lo[j] = *(uint32_t*)&l2;
}

// ---------------------------------------------------------------------------
// prep 6: split input x (row-major k-pairs)
// ---------------------------------------------------------------------------
__global__ void split_rowmajor_kernel(const float* __restrict__ in,
                                      uint32_t* __restrict__ hi, uint32_t* __restrict__ lo,
                                      int nPairs) {
    int i = blockIdx.x * blockDim.x + threadIdx.x;
    if (i >= nPairs) return;
    float2 v = ((const float2*)in)[i];
    __nv_bfloat162 h2 = __floats2bfloat162_rn(v.x, v.y);
    float r0 = v.x - __bfloat162float(h2.x);
    float r1 = v.y - __bfloat162float(h2.y);
    __nv_bfloat162 l2 = __floats2bfloat162_rn(r0, r1);
    hi[i] = *(uint32_t*)&h2;
    lo[i] = *(uint32_t*)&l2;
}

// ---------------------------------------------------------------------------
// bf16 split tensor-core GEMM: C = Ah@Bh + Ah@Bl + Al@Bh  (fp32 accum)
// Block 128x128, 8 warps (warp tile 32x64), mma.sync m16n8k16.bf16.
// Double-buffered SMEM, 24 iterations = 3 phases x 8 k-tiles. (verified R13)
// ---------------------------------------------------------------------------
#define BM 128
#define BN 128
#define KW 16   // k2 words per tile (=32 k values)
#define ASTRIDE (KW + 4)   // 20 words: conflict-free
#define BSTRIDE (BN + 8)   // 136 words: conflict-free

__device__ __forceinline__ void mma_bf16(float* c, const uint32_t* a, const uint32_t* b) {
    asm volatile(
        "mma.sync.aligned.m16n8k16.row.col.f32.bf16.bf16.f32 "
        "{%0,%1,%2,%3}, {%4,%5,%6,%7}, {%8,%9}, {%0,%1,%2,%3};"
        : "+f"(c[0]), "+f"(c[1]), "+f"(c[2]), "+f"(c[3])
        : "r"(a[0]), "r"(a[1]), "r"(a[2]), "r"(a[3]), "r"(b[0]), "r"(b[1]));
}

__global__ __launch_bounds__(256) void bgemm_kernel(
    const uint32_t* __restrict__ Ah, const uint32_t* __restrict__ Al,
    const uint32_t* __restrict__ Bh, const uint32_t* __restrict__ Bl,
    float* __restrict__ C, int M) {
    __shared__ uint32_t As2[2][BM * ASTRIDE];
    __shared__ uint32_t Bs2[2][KW * BSTRIDE];

    const int tid = threadIdx.x;
    const int lane = tid & 31;
    const int wid = tid >> 5;
    const int warpM = wid & 3;
    const int warpN = wid >> 2;
    const int g = lane >> 2;
    const int t = lane & 3;
    const int rowBase = blockIdx.x * BM;
    const int colBase = blockIdx.y * BN;

    const int q0 = tid * 2, q1 = q0 + 1;
    const int ar0 = q0 >> 2, aw0 = (q0 & 3) << 2;
    const int ar1 = q1 >> 2, aw1 = (q1 & 3) << 2;
    const int grow0 = rowBase + ar0, grow1 = rowBase + ar1;
    const int bq0 = tid * 2, bq1 = bq0 + 1;
    const int br0 = bq0 >> 5, bw0 = (bq0 & 31) << 2;
    const int br1 = bq1 >> 5, bw1 = (bq1 & 31) << 2;

    const uint32_t* APtrs[3] = {Ah, Ah, Al};
    const uint32_t* BPtrs[3] = {Bh, Bl, Bh};

    float c[2][8][4];
#pragma unroll
    for (int mt = 0; mt < 2; mt++)
#pragma unroll
        for (int nt = 0; nt < 8; nt++)
#pragma unroll
            for (int r = 0; r < 4; r++) c[mt][nt][r] = 0.0f;

    uint4 pa0, pa1, pb0, pb1;
    {
        const uint32_t* Ap = APtrs[0];
        const uint32_t* Bp = BPtrs[0];
        pa0 = (grow0 < M) ? *(const uint4*)(Ap + (size_t)grow0 * KP + aw0)
                          : make_uint4(0, 0, 0, 0);
        pa1 = (grow1 < M) ? *(const uint4*)(Ap + (size_t)grow1 * KP + aw1)
                          : make_uint4(0, 0, 0, 0);
        pb0 = *(const uint4*)(Bp + (size_t)br0 * D + colBase + bw0);
        pb1 = *(const uint4*)(Bp + (size_t)br1 * D + colBase + bw1);
        *(uint4*)&As2[0][ar0 * ASTRIDE + aw0] = pa0;
        *(uint4*)&As2[0][ar1 * ASTRIDE + aw1] = pa1;
        *(uint4*)&Bs2[0][br0 * BSTRIDE + bw0] = pb0;
        *(uint4*)&Bs2[0][br1 * BSTRIDE + bw1] = pb1;
    }
    __syncthreads();

    for (int it = 0; it < 24; it++) {
        const int cur = it & 1;
        const bool more = (it + 1 < 24);
        if (more) {
            int nx = it + 1;
            int p = nx >> 3;
            int kw0 = (nx & 7) * KW;
            const uint32_t* Ap = APtrs[p];
            const uint32_t* Bp = BPtrs[p];
            pa0 = (grow0 < M) ? *(const uint4*)(Ap + (size_t)grow0 * KP + kw0 + aw0)
                              : make_uint4(0, 0, 0, 0);
            pa1 = (grow1 < M) ? *(const uint4*)(Ap + (size_t)grow1 * KP + kw0 + aw1)
                              : make_uint4(0, 0, 0, 0);
            pb0 = *(const uint4*)(Bp + (size_t)(kw0 + br0) * D + colBase + bw0);
            pb1 = *(const uint4*)(Bp + (size_t)(kw0 + br1) * D + colBase + bw1);
        }

        const uint32_t* Asc = As2[cur];
        const uint32_t* Bsc = Bs2[cur];
#pragma unroll
        for (int ks = 0; ks < 2; ks++) {
            const int kb = ks * 8;
            uint32_t a[2][4], b[8][2];
#pragma unroll
            for (int mt = 0; mt < 2; mt++) {
                int m0 = warpM * 32 + mt * 16;
                a[mt][0] = Asc[(m0 + g) * ASTRIDE + kb + t];
                a[mt][1] = Asc[(m0 + g + 8) * ASTRIDE + kb + t];
                a[mt][2] = Asc[(m0 + g) * ASTRIDE + kb + t + 4];
                a[mt][3] = Asc[(m0 + g + 8) * ASTRIDE + kb + t + 4];
            }
#pragma unroll
            for (int nt = 0; nt < 8; nt++) {
                int n0 = warpN * 64 + nt * 8;
                b[nt][0] = Bsc[(kb + t) * BSTRIDE + n0 + g];
                b[nt][1] = Bsc[(kb + t + 4) * BSTRIDE + n0 + g];
            }
#pragma unroll
            for (int mt = 0; mt < 2; mt++)
#pragma unroll
                for (int nt = 0; nt < 8; nt++)
                    mma_bf16(c[mt][nt], a[mt], b[nt]);
        }

        if (more) {
            const int nxt = 1 - cur;
            *(uint4*)&As2[nxt][ar0 * ASTRIDE + aw0] = pa0;
            *(uint4*)&As2[nxt][ar1 * ASTRIDE + aw1] = pa1;
            *(uint4*)&Bs2[nxt][br0 * BSTRIDE + bw0] = pb0;
            *(uint4*)&Bs2[nxt][br1 * BSTRIDE + bw1] = pb1;
        }
        __syncthreads();
    }

#pragma unroll
    for (int mt = 0; mt < 2; mt++) {
#pragma unroll
        for (int nt = 0; nt < 8; nt++) {
            int row0 = rowBase + warpM * 32 + mt * 16 + g;
            int col = colBase + warpN * 64 + nt * 8 + t * 2;
            if (row0 < M)
                *(float2*)(C + (size_t)row0 * D + col) =
                    make_float2(c[mt][nt][0], c[mt][nt][1]);
            if (row0 + 8 < M)
                *(float2*)(C + (size_t)(row0 + 8) * D + col) =
                    make_float2(c[mt][nt][2], c[mt][nt][3]);
        }
    }
}

// ---------------------------------------------------------------------------
// Fused gather: warp-per-node (R13-proven simple loop).
// acc = h[n,:]*dinv^2 + sum_in-edges h[src,:]*w + b; relu.
// writePacked=1: emit bf16 hi/lo packed (feeds next GEMM). Else write fp32.
// ---------------------------------------------------------------------------
__global__ __launch_bounds__(256) void gather_kernel(
    const float* __restrict__ h,
    const int* __restrict__ rowstart,
    const int* __restrict__ csr_src,
    const float* __restrict__ csr_w,
    const float* __restrict__ dinv,
    const float* __restrict__ bias,
    float* __restrict__ out,
    uint32_t* __restrict__ outHi,
    uint32_t* __restrict__ outLo,
    int writePacked) {
    int node = (blockIdx.x * blockDim.x + threadIdx.x) >> 5;
    if (node >= N_NODES) return;
    int lane = threadIdx.x & 31;

    float dv = dinv[node];
    float w0 = dv * dv;
    const float4* selfp = (const float4*)(h + (size_t)node * D);
    float4 a0 = selfp[lane];
    float4 a1 = selfp[lane + 32];
    a0.x *= w0; a0.y *= w0; a0.z *= w0; a0.w *= w0;
    a1.x *= w0; a1.y *= w0; a1.z *= w0; a1.w *= w0;

    int beg = rowstart[node];
    int end = rowstart[node + 1];
    for (int j = beg; j < end; j++) {
        int s = __ldg(&csr_src[j]);
        float w = __ldg(&csr_w[j]);
        const float4* sp = (const float4*)(h + (size_t)s * D);
        float4 v0 = sp[lane];
        float4 v1 = sp[lane + 32];
        a0.x = fmaf(v0.x, w, a0.x); a0.y = fmaf(v0.y, w, a0.y);
        a0.z = fmaf(v0.z, w, a0.z); a0.w = fmaf(v0.w, w, a0.w);
        a1.x = fmaf(v1.x, w, a1.x); a1.y = fmaf(v1.y, w, a1.y);
        a1.z = fmaf(v1.z, w, a1.z); a1.w = fmaf(v1.w, w, a1.w);
    }

    const float4* b4 = (const float4*)bias;
    float4 bb0 = b4[lane];
    float4 bb1 = b4[lane + 32];
    a0.x = fmaxf(a0.x + bb0.x, 0.f); a0.y = fmaxf(a0.y + bb0.y, 0.f);
    a0.z = fmaxf(a0.z + bb0.z, 0.f); a0.w = fmaxf(a0.w + bb0.w, 0.f);
    a1.x = fmaxf(a1.x + bb1.x, 0.f); a1.y = fmaxf(a1.y + bb1.y, 0.f);
    a1.z = fmaxf(a1.z + bb1.z, 0.f); a1.w = fmaxf(a1.w + bb1.w, 0.f);

    if (writePacked) {
        size_t base = (size_t)node * KP;
        __nv_bfloat162 h00 = __floats2bfloat162_rn(a0.x, a0.y);
        __nv_bfloat162 h01 = __floats2bfloat162_rn(a0.z, a0.w);
        __nv_bfloat162 h10 = __floats2bfloat162_rn(a1.x, a1.y);
        __nv_bfloat162 h11 = __floats2bfloat162_rn(a1.z, a1.w);
        __nv_bfloat162 l00 = __floats2bfloat162_rn(a0.x - __bfloat162float(h00.x),
                                                   a0.y - __bfloat162float(h00.y));
        __nv_bfloat162 l01 = __floats2bfloat162_rn(a0.z - __bfloat162float(h01.x),
                                                   a0.w - __bfloat162float(h01.y));
        __nv_bfloat162 l10 = __floats2bfloat162_rn(a1.x - __bfloat162float(h10.x),
                                                   a1.y - __bfloat162float(h10.y));
        __nv_bfloat162 l11 = __floats2bfloat162_rn(a1.z - __bfloat162float(h11.x),
                                                   a1.w - __bfloat162float(h11.y));
        *(uint2*)&outHi[base + 2 * lane] = make_uint2(*(uint32_t*)&h00, *(uint32_t*)&h01);
        *(uint2*)&outHi[base + 64 + 2 * lane] = make_uint2(*(uint32_t*)&h10, *(uint32_t*)&h11);
        *(uint2*)&outLo[base + 2 * lane] = make_uint2(*(uint32_t*)&l00, *(uint32_t*)&l01);
        *(uint2*)&outLo[base + 64 + 2 * lane] = make_uint2(*(uint32_t*)&l10, *(uint32_t*)&l11);
    } else {
        float4* op = (float4*)(out + (size_t)node * D);
        op[lane] = a0;
        op[lane + 32] = a1;
    }
}

// ---------------------------------------------------------------------------
// Launch
// ---------------------------------------------------------------------------
extern "C" void kernel_launch(void* const* d_in, const int* in_sizes, int n_in,
                              void* d_out, int out_size) {
    const float* x = (const float*)d_in[0];
    const void* ei = d_in[1];
    const float* W1 = (const float*)d_in[2];
    const float* b1 = (const float*)d_in[3];
    const float* W2 = (const float*)d_in[4];
    const float* b2 = (const float*)d_in[5];
    float* out = (float*)d_out;

    float *h, *dinv, *csr_w;
    int *srcI, *dstI, *cnt, *cursor, *rowstart, *csr_src;
    uint32_t *ah, *al, *w1h, *w1l, *w2h, *w2l;
    cudaGetSymbolAddress((void**)&h, g_h);
    cudaGetSymbolAddress((void**)&dinv, g_dinv);
    cudaGetSymbolAddress((void**)&cnt, g_cnt);
    cudaGetSymbolAddress((void**)&cursor, g_cursor);
    cudaGetSymbolAddress((void**)&rowstart, g_rowstart);
    cudaGetSymbolAddress((void**)&csr_src, g_csr_src);
    cudaGetSymbolAddress((void**)&csr_w, g_csr_w);
    cudaGetSymbolAddress((void**)&srcI, g_src);
    cudaGetSymbolAddress((void**)&dstI, g_dst);
    cudaGetSymbolAddress((void**)&ah, g_ah);
    cudaGetSymbolAddress((void**)&al, g_al);
    cudaGetSymbolAddress((void**)&w1h, g_w1h);
    cudaGetSymbolAddress((void**)&w1l, g_w1l);
    cudaGetSymbolAddress((void**)&w2h, g_w2h);
    cudaGetSymbolAddress((void**)&w2l, g_w2l);

    const int TPB = 256;
    const int gN = (N_NODES + TPB - 1) / TPB;
    const int gE = (N_EDGES + TPB - 1) / TPB;
    const int gGather = (int)(((long long)N_NODES * 32 + TPB - 1) / TPB);
    const int nPairsA = N_NODES * KP;
    const int gSplitA = (nPairsA + TPB - 1) / TPB;
    const int gSplitW2 = (2 * KP * D + TPB - 1) / TPB;
    dim3 gGemm((N_NODES + BM - 1) / BM, D / BN);

    // ---- prep (6 launches) ----
    prep_zero_detect_kernel<<<gN, TPB>>>((const unsigned int*)ei, cnt, cursor);
    convert_count_kernel<<<gE, TPB>>>(ei, srcI, dstI, cnt);
    scan_dinv_kernel<<<1, 1024>>>(cnt, rowstart, dinv);
    fill_kernel<<<gE, TPB>>>(srcI, dstI, rowstart, cursor, dinv, csr_src, csr_w);
    split_both_w_kernel<<<gSplitW2, TPB>>>(W1, W2, w1h, w1l, w2h, w2l);
    split_rowmajor_kernel<<<gSplitA, TPB>>>(x, ah, al, nPairsA);

    // ---- layer 1 ----
    bgemm_kernel<<<gGemm, TPB>>>(ah, al, w1h, w1l, h, N_NODES);
    gather_kernel<<<gGather, TPB>>>(h, rowstart, csr_src, csr_w, dinv, b1,
                                    (float*)nullptr, ah, al, 1);

    // ---- layer 2 ----
    bgemm_kernel<<<gGemm, TPB>>>(ah, al, w2h, w2l, h, N_NODES);
    gather_kernel<<<gGather, TPB>>>(h, rowstart, csr_src, csr_w, dinv, b2,
                                    out, (uint32_t*)nullptr, (uint32_t*)nullptr, 0);
}